// round 10
// baseline (speedup 1.0000x reference)
#include <cuda_runtime.h>
#include <cuda_bf16.h>
#include <stdint.h>

// m=n=8192, k=64 fixed. Output dtype: float32 (quantized integer values).
#define COLS   8192
#define KDIM   64
#define GRIDN  296              // 2 persistent CTAs per SM
#define THREADS 256

// smem layout (32-bit words)
#define XS_STRIDE 36                     // words per chunk (32 bf16x2 + pad)
#define XS_BUF    (128*XS_STRIDE)        // 4608 words per split plane
#define XS_TOTAL  (2*2*XS_BUF)           // 18432: 2 buffers x 2 split planes
#define HS_STRIDE 72                     // words per k-pair row
#define HS_PLANE  (32*HS_STRIDE)         // 2304 words per split plane
#define HS_TOTAL  (2*HS_PLANE)           // 4608
#define RED_OFF   (XS_TOTAL + HS_TOTAL)  // 23040
#define SMEM_WORDS (RED_OFF + 32)
#define SMEM_BYTES (SMEM_WORDS*4)        // 92288 B -> 2 CTAs/SM

#define MMA16(dd, A, B)                                                        \
    asm volatile("mma.sync.aligned.m16n8k16.row.col.f32.bf16.bf16.f32 "        \
        "{%0,%1,%2,%3}, {%4,%5,%6,%7}, {%8,%9}, {%0,%1,%2,%3};"                \
        : "+f"((dd)[0]), "+f"((dd)[1]), "+f"((dd)[2]), "+f"((dd)[3])           \
        : "r"((A)[0]), "r"((A)[1]), "r"((A)[2]), "r"((A)[3]),                  \
          "r"((B)[0]), "r"((B)[1]))

__device__ __forceinline__ void split2f(float v, float& f1, float& f2) {
    f1 = __bfloat162float(__float2bfloat16(v));
    f2 = __bfloat162float(__float2bfloat16(v - f1));
}
// pack two f32 (already bf16-rounded) into bf16x2: lo in low half
__device__ __forceinline__ uint32_t packbf(float lo, float hi) {
    return __byte_perm(__float_as_uint(lo), __float_as_uint(hi), 0x7632);
}

// thread t owns chunk c=t>>1, half (t&1): 32 floats
__device__ __forceinline__ void load_raw(const float* __restrict__ src, int t, float4 raw[8]) {
    const float4* p = (const float4*)(src + (t >> 1) * 64 + (t & 1) * 32);
    #pragma unroll
    for (int i = 0; i < 8; ++i) raw[i] = p[i];
}

__device__ __forceinline__ void split_sts(uint32_t* sm, int buf, int t, const float4 raw[8]) {
    const int c = t >> 1, ip0 = (t & 1) << 4;   // word offset within chunk
    uint32_t w1[16], w2[16];
    #pragma unroll
    for (int p = 0; p < 8; ++p) {
        float a1, a2, b1, b2;
        split2f(raw[p].x, a1, a2); split2f(raw[p].y, b1, b2);
        w1[p*2]   = packbf(a1, b1); w2[p*2]   = packbf(a2, b2);
        split2f(raw[p].z, a1, a2); split2f(raw[p].w, b1, b2);
        w1[p*2+1] = packbf(a1, b1); w2[p*2+1] = packbf(a2, b2);
    }
    uint32_t* base = sm + buf * 2 * XS_BUF + c * XS_STRIDE + ip0;
    #pragma unroll
    for (int q = 0; q < 4; ++q)
        *(uint4*)(base + q * 4) = make_uint4(w1[q*4], w1[q*4+1], w1[q*4+2], w1[q*4+3]);
    base += XS_BUF;
    #pragma unroll
    for (int q = 0; q < 4; ++q)
        *(uint4*)(base + q * 4) = make_uint4(w2[q*4], w2[q*4+1], w2[q*4+2], w2[q*4+3]);
}

__global__ __launch_bounds__(THREADS, 2)
void bdq8_kernel(const float* __restrict__ x, const float* __restrict__ hmat,
                 float* __restrict__ out, int nrows)
{
    extern __shared__ uint32_t sm[];
    float* redf = (float*)(sm + RED_OFF);

    const int t  = threadIdx.x;
    const int w  = t >> 5, L = t & 31;
    const int g  = L >> 2, tq = L & 3;      // quad layout
    const int c0 = w * 16 + g;              // A fragment row (chunk); warp = m-tile

    // ---- h -> 2 bf16 split planes (once per kernel) ----
    {
        const int j = t & 63;
        const int kp0 = (t >> 6) * 8;
        #pragma unroll
        for (int p = 0; p < 8; ++p) {
            const int kp = kp0 + p;
            const float ve = hmat[(2*kp)   * 64 + j];   // even k
            const float vo = hmat[(2*kp+1) * 64 + j];   // odd k
            float e1, e2, o1, o2;
            split2f(ve, e1, e2); split2f(vo, o1, o2);
            uint32_t* hb = sm + XS_TOTAL + kp * HS_STRIDE + j;
            hb[0]        = packbf(e1, o1);
            hb[HS_PLANE] = packbf(e2, o2);
        }
    }

    // ---- first row -> buffer 0 ----
    long row = blockIdx.x;
    {
        float4 raw[8];
        if (row < nrows) {
            load_raw(x + row * (long)COLS, t, raw);
            split_sts(sm, 0, t, raw);
        }
    }
    __syncthreads();

    int buf = 0;
    for (; row < nrows; row += GRIDN) {
        // ---- prefetch next row into registers (hidden under MMA) ----
        const long nxt = row + GRIDN;
        float4 raw[8];
        if (nxt < nrows) load_raw(x + nxt * (long)COLS, t, raw);

        // ---- MMA mainloop: 4 k-tiles x 8 n-tiles x 3 split-products ----
        float d[8][4];
        #pragma unroll
        for (int nt = 0; nt < 8; ++nt)
            #pragma unroll
            for (int e = 0; e < 4; ++e) d[nt][e] = 0.0f;

        const uint32_t* xsb = sm + buf * 2 * XS_BUF;

        #pragma unroll
        for (int kt = 0; kt < 4; ++kt) {
            uint32_t A[2][4];
            #pragma unroll
            for (int s = 0; s < 2; ++s) {
                const uint32_t* pa = xsb + s*XS_BUF + c0*XS_STRIDE + kt*8 + tq;
                A[s][0] = pa[0];
                A[s][1] = pa[8 * XS_STRIDE];
                A[s][2] = pa[4];
                A[s][3] = pa[8 * XS_STRIDE + 4];
            }
            #pragma unroll
            for (int nt = 0; nt < 8; ++nt) {
                const uint32_t* pb = sm + XS_TOTAL + (kt*8 + tq)*HS_STRIDE + nt*8 + g;
                uint32_t B0[2], B1[2];
                B0[0] = pb[0];          B0[1] = pb[4*HS_STRIDE];
                B1[0] = pb[HS_PLANE];   B1[1] = pb[HS_PLANE + 4*HS_STRIDE];
                MMA16(d[nt], A[0], B0);     // x1*h1
                MMA16(d[nt], A[0], B1);     // x1*h2
                MMA16(d[nt], A[1], B0);     // x2*h1
            }
        }

        // ---- row absmax ----
        float m = 0.0f;
        #pragma unroll
        for (int nt = 0; nt < 8; ++nt)
            #pragma unroll
            for (int e = 0; e < 4; ++e)
                m = fmaxf(m, fabsf(d[nt][e]));
        #pragma unroll
        for (int o = 16; o > 0; o >>= 1)
            m = fmaxf(m, __shfl_xor_sync(0xffffffffu, m, o));
        if (L == 0) redf[w] = m;
        __syncthreads();
        float a = redf[0];
        #pragma unroll
        for (int ww = 1; ww < 8; ++ww) a = fmaxf(a, redf[ww]);
        const float inv = (a == 0.0f) ? 0.0f : __fdiv_rn(127.0f, a);

        // ---- quantize (round-half-even) + store float32 ----
        float* orow = out + row * (long)COLS;
        #pragma unroll
        for (int nt = 0; nt < 8; ++nt) {
            const int j0 = nt*8 + tq*2;
            float q0 = fminf(fmaxf(rintf(d[nt][0] * inv), -128.0f), 127.0f);
            float q1 = fminf(fmaxf(rintf(d[nt][1] * inv), -128.0f), 127.0f);
            float q2 = fminf(fmaxf(rintf(d[nt][2] * inv), -128.0f), 127.0f);
            float q3 = fminf(fmaxf(rintf(d[nt][3] * inv), -128.0f), 127.0f);
            *(float2*)(orow + c0*64 + j0)     = make_float2(q0, q1);
            *(float2*)(orow + (c0+8)*64 + j0) = make_float2(q2, q3);
        }

        // ---- stage next row into the other buffer ----
        if (nxt < nrows) split_sts(sm, buf ^ 1, t, raw);
        __syncthreads();
        buf ^= 1;
    }
}

extern "C" void kernel_launch(void* const* d_in, const int* in_sizes, int n_in,
                              void* d_out, int out_size)
{
    const float* x;
    const float* h;
    long x_elems;
    if (in_sizes[0] > in_sizes[1]) {
        x = (const float*)d_in[0]; h = (const float*)d_in[1]; x_elems = in_sizes[0];
    } else {
        x = (const float*)d_in[1]; h = (const float*)d_in[0]; x_elems = in_sizes[1];
    }
    const int nrows = (int)(x_elems / COLS);

    cudaFuncSetAttribute(bdq8_kernel, cudaFuncAttributeMaxDynamicSharedMemorySize, SMEM_BYTES);
    bdq8_kernel<<<GRIDN, THREADS, SMEM_BYTES>>>(x, h, (float*)d_out, nrows);
}

// round 11
// speedup vs baseline: 1.9883x; 1.9883x over previous
#include <cuda_runtime.h>
#include <cuda_bf16.h>
#include <stdint.h>

// m=n=8192, k=64 fixed. Output dtype: float32 (quantized integer values).
#define COLS   8192
#define KDIM   64
#define GRIDN  296               // 2 persistent CTAs per SM
#define THREADS 256

// smem word offsets
#define XS_STRIDE 36                    // words per chunk (32 bf16x2 + pad)
#define XS_PLANE  (128*XS_STRIDE)       // 4608 words
#define HS_STRIDE 72                    // words per k-pair row
#define HS_PLANE  (32*HS_STRIDE)        // 2304 words
#define OFF_XS1   0
#define OFF_XS2   XS_PLANE
#define OFF_H1    (2*XS_PLANE)          // 9216
#define OFF_H2    (OFF_H1 + HS_PLANE)   // 11520
#define OFF_RAW   (OFF_H2 + HS_PLANE)   // 13824 (8192 words raw row)
#define OFF_RED   (OFF_RAW + 8192)      // 22016
#define SMEM_WORDS (OFF_RED + 32)
#define SMEM_BYTES (SMEM_WORDS*4)       // 88192 B -> 2 CTAs/SM

#define MMA16(dd, A, B)                                                        \
    asm volatile("mma.sync.aligned.m16n8k16.row.col.f32.bf16.bf16.f32 "        \
        "{%0,%1,%2,%3}, {%4,%5,%6,%7}, {%8,%9}, {%0,%1,%2,%3};"                \
        : "+f"((dd)[0]), "+f"((dd)[1]), "+f"((dd)[2]), "+f"((dd)[3])           \
        : "r"((A)[0]), "r"((A)[1]), "r"((A)[2]), "r"((A)[3]),                  \
          "r"((B)[0]), "r"((B)[1]))

__device__ __forceinline__ void split2f(float v, float& f1, float& f2) {
    f1 = __bfloat162float(__float2bfloat16(v));
    f2 = __bfloat162float(__float2bfloat16(v - f1));
}
__device__ __forceinline__ uint32_t packbf(float lo, float hi) {
    return __byte_perm(__float_as_uint(lo), __float_as_uint(hi), 0x7632);
}

// coalesced cp.async of one row (8192 floats) into raw buffer
__device__ __forceinline__ void stage_raw(uint32_t* sm, const float* __restrict__ src, int t) {
    #pragma unroll
    for (int p = 0; p < 8; ++p) {
        const int n = p * 1024 + t * 4;
        asm volatile("cp.async.cg.shared.global [%0], [%1], 16;"
            :: "r"((uint32_t)__cvta_generic_to_shared((float*)(sm + OFF_RAW) + n)),
               "l"(src + n));
    }
}

// split raw row -> 2 bf16x2 planes (conflict-free LDS.128 reads, STS.64 writes)
__device__ __forceinline__ void split_row(uint32_t* sm, int t) {
    const int w = t >> 5, L = t & 31;
    const float* raw = (const float*)(sm + OFF_RAW) + w * 1024 + L * 4;
    const int cbase = w * 16 + (L >> 4);
    const int ip    = (L & 15) * 2;
    #pragma unroll
    for (int i = 0; i < 8; ++i) {
        const float4 v = *(const float4*)(raw + i * 128);
        float a1, a2, b1, b2, c1, c2, e1, e2;
        split2f(v.x, a1, a2); split2f(v.y, b1, b2);
        split2f(v.z, c1, c2); split2f(v.w, e1, e2);
        const int c = cbase + i * 2;
        *(uint2*)(sm + OFF_XS1 + c * XS_STRIDE + ip) =
            make_uint2(packbf(a1, b1), packbf(c1, e1));
        *(uint2*)(sm + OFF_XS2 + c * XS_STRIDE + ip) =
            make_uint2(packbf(a2, b2), packbf(c2, e2));
    }
}

__global__ __launch_bounds__(THREADS, 2)
void bdq9_kernel(const float* __restrict__ x, const float* __restrict__ hmat,
                 float* __restrict__ out, int nrows)
{
    extern __shared__ uint32_t sm[];
    float* redf = (float*)(sm + OFF_RED);

    const int t  = threadIdx.x;
    const int w  = t >> 5, L = t & 31;
    const int g  = L >> 2, tq = L & 3;       // quad layout
    const int mw = w & 3,  nw = w >> 2;      // warp tile: 32 chunks x 32 cols

    long row = blockIdx.x;

    // ---- issue first row early (coalesced) ----
    if (row < nrows) stage_raw(sm, x + row * (long)COLS, t);
    asm volatile("cp.async.commit_group;");

    // ---- h -> 2 bf16x2 planes ----
    {
        const int j = t & 63;
        const int kp0 = (t >> 6) * 8;
        #pragma unroll
        for (int p = 0; p < 8; ++p) {
            const int kp = kp0 + p;
            const float ve = hmat[(2 * kp)     * 64 + j];
            const float vo = hmat[(2 * kp + 1) * 64 + j];
            float e1, e2, o1, o2;
            split2f(ve, e1, e2); split2f(vo, o1, o2);
            sm[OFF_H1 + kp * HS_STRIDE + j] = packbf(e1, o1);
            sm[OFF_H2 + kp * HS_STRIDE + j] = packbf(e2, o2);
        }
    }

    asm volatile("cp.async.wait_group 0;");
    __syncthreads();

    if (row < nrows) split_row(sm, t);
    __syncthreads();

    // ---- stage row+GRIDN while first row computes ----
    if (row + GRIDN < nrows) stage_raw(sm, x + (row + GRIDN) * (long)COLS, t);
    asm volatile("cp.async.commit_group;");

    // ---- hold h1 B-fragments in registers for the whole kernel ----
    uint32_t Bh1[4][4][2];
    #pragma unroll
    for (int kt = 0; kt < 4; ++kt)
        #pragma unroll
        for (int nt = 0; nt < 4; ++nt) {
            const uint32_t* pb = sm + OFF_H1 + (kt * 8 + tq) * HS_STRIDE + nw * 32 + nt * 8 + g;
            Bh1[kt][nt][0] = pb[0];
            Bh1[kt][nt][1] = pb[4 * HS_STRIDE];
        }

    for (; row < nrows; row += GRIDN) {
        // ===== MMA: 4 kt x 4 nt x 2 mfrag x 4 products =====
        float d[2][4][4];
        #pragma unroll
        for (int mf = 0; mf < 2; ++mf)
            #pragma unroll
            for (int nt = 0; nt < 4; ++nt)
                #pragma unroll
                for (int e = 0; e < 4; ++e) d[mf][nt][e] = 0.0f;

        #pragma unroll
        for (int kt = 0; kt < 4; ++kt) {
            uint32_t A1[2][4], A2[2][4];
            #pragma unroll
            for (int mf = 0; mf < 2; ++mf) {
                const uint32_t* pa = sm + OFF_XS1 + (mw * 32 + mf * 16 + g) * XS_STRIDE + kt * 8 + tq;
                A1[mf][0] = pa[0];
                A1[mf][1] = pa[8 * XS_STRIDE];
                A1[mf][2] = pa[4];
                A1[mf][3] = pa[8 * XS_STRIDE + 4];
                pa += (OFF_XS2 - OFF_XS1);
                A2[mf][0] = pa[0];
                A2[mf][1] = pa[8 * XS_STRIDE];
                A2[mf][2] = pa[4];
                A2[mf][3] = pa[8 * XS_STRIDE + 4];
            }
            #pragma unroll
            for (int nt = 0; nt < 4; ++nt) {
                const uint32_t* pb = sm + OFF_H2 + (kt * 8 + tq) * HS_STRIDE + nw * 32 + nt * 8 + g;
                uint32_t B2[2];
                B2[0] = pb[0];
                B2[1] = pb[4 * HS_STRIDE];
                #pragma unroll
                for (int mf = 0; mf < 2; ++mf) {
                    MMA16(d[mf][nt], A1[mf], Bh1[kt][nt]);   // x1*h1
                    MMA16(d[mf][nt], A1[mf], B2);            // x1*h2
                    MMA16(d[mf][nt], A2[mf], Bh1[kt][nt]);   // x2*h1
                    MMA16(d[mf][nt], A2[mf], B2);            // x2*h2
                }
            }
        }

        // ---- row absmax ----
        float m = 0.0f;
        #pragma unroll
        for (int mf = 0; mf < 2; ++mf)
            #pragma unroll
            for (int nt = 0; nt < 4; ++nt)
                #pragma unroll
                for (int e = 0; e < 4; ++e)
                    m = fmaxf(m, fabsf(d[mf][nt][e]));
        #pragma unroll
        for (int o = 16; o > 0; o >>= 1)
            m = fmaxf(m, __shfl_xor_sync(0xffffffffu, m, o));
        if (L == 0) redf[w] = m;
        __syncthreads();
        float a = redf[0];
        #pragma unroll
        for (int ww = 1; ww < 8; ++ww) a = fmaxf(a, redf[ww]);
        const float inv = (a == 0.0f) ? 0.0f : __fdiv_rn(127.0f, a);

        // ---- quantize (round-half-even) + store float32 ----
        float* orow = out + row * (long)COLS;
        #pragma unroll
        for (int mf = 0; mf < 2; ++mf) {
            const int c0 = mw * 32 + mf * 16 + g;
            #pragma unroll
            for (int nt = 0; nt < 4; ++nt) {
                const int j0 = nw * 32 + nt * 8 + tq * 2;
                float q0 = fminf(fmaxf(rintf(d[mf][nt][0] * inv), -128.0f), 127.0f);
                float q1 = fminf(fmaxf(rintf(d[mf][nt][1] * inv), -128.0f), 127.0f);
                float q2 = fminf(fmaxf(rintf(d[mf][nt][2] * inv), -128.0f), 127.0f);
                float q3 = fminf(fmaxf(rintf(d[mf][nt][3] * inv), -128.0f), 127.0f);
                *(float2*)(orow + c0 * 64 + j0)       = make_float2(q0, q1);
                *(float2*)(orow + (c0 + 8) * 64 + j0) = make_float2(q2, q3);
            }
        }

        // ---- pipeline: raw(row+GRIDN) -> planes; issue raw(row+2*GRIDN) ----
        const long nxt = row + GRIDN;
        asm volatile("cp.async.wait_group 0;");
        __syncthreads();                 // raw ready; all plane reads done
        if (nxt < nrows) split_row(sm, t);
        __syncthreads();                 // planes written; raw reads done
        if (nxt + GRIDN < nrows)
            stage_raw(sm, x + (nxt + GRIDN) * (long)COLS, t);
        asm volatile("cp.async.commit_group;");
    }
}

extern "C" void kernel_launch(void* const* d_in, const int* in_sizes, int n_in,
                              void* d_out, int out_size)
{
    const float* x;
    const float* h;
    long x_elems;
    if (in_sizes[0] > in_sizes[1]) {
        x = (const float*)d_in[0]; h = (const float*)d_in[1]; x_elems = in_sizes[0];
    } else {
        x = (const float*)d_in[1]; h = (const float*)d_in[0]; x_elems = in_sizes[1];
    }
    const int nrows = (int)(x_elems / COLS);

    cudaFuncSetAttribute(bdq9_kernel, cudaFuncAttributeMaxDynamicSharedMemorySize, SMEM_BYTES);
    bdq9_kernel<<<GRIDN, THREADS, SMEM_BYTES>>>(x, h, (float*)d_out, nrows);
}